// round 10
// baseline (speedup 1.0000x reference)
#include <cuda_runtime.h>
#include <cuda_bf16.h>
#include <cstdint>

#define NCTX 2048
#define DH   64
#define BH   32      // B*H for this problem
#define QM   128     // q rows per CTA
#define TN   64      // kv tokens per tile
#define NTH  256     // 8 warps
#define KROW 72      // smem row stride in bf16 elems (144B, ldmatrix conflict-free)
#define PLANE ((size_t)BH * NCTX * DH)         // elems per bf16 plane
#define BUFB  (TN * KROW * 2)                  // 9216 bytes per smem buffer
#define STAGEB (4 * BUFB)                      // 36864 bytes per stage

// persistent scratch: Kh | Kl | Vh | Vl planes, each [BH*NCTX][DH] bf16 (32MB total)
__device__ uint16_t gKV[4 * BH * NCTX * DH];

static __device__ __forceinline__ uint32_t smem_u32(const void* p) {
    uint32_t a;
    asm("{ .reg .u64 t; cvta.to.shared.u64 t, %1; cvt.u32.u64 %0, t; }" : "=r"(a) : "l"(p));
    return a;
}

#define MMA(d, a, b) \
    asm volatile("mma.sync.aligned.m16n8k16.row.col.f32.bf16.bf16.f32 " \
        "{%0,%1,%2,%3}, {%4,%5,%6,%7}, {%8,%9}, {%0,%1,%2,%3};" \
        : "+f"((d)[0]), "+f"((d)[1]), "+f"((d)[2]), "+f"((d)[3]) \
        : "r"((a)[0]), "r"((a)[1]), "r"((a)[2]), "r"((a)[3]), "r"((b)[0]), "r"((b)[1]))

#define LDSM4(r, addr) \
    asm volatile("ldmatrix.sync.aligned.m8n8.x4.shared.b16 {%0,%1,%2,%3}, [%4];" \
        : "=r"((r)[0]), "=r"((r)[1]), "=r"((r)[2]), "=r"((r)[3]) : "r"(addr))

#define LDSM4T(r, addr) \
    asm volatile("ldmatrix.sync.aligned.m8n8.x4.trans.shared.b16 {%0,%1,%2,%3}, [%4];" \
        : "=r"((r)[0]), "=r"((r)[1]), "=r"((r)[2]), "=r"((r)[3]) : "r"(addr))

static __device__ __forceinline__ void split_pair(float a, float b, uint32_t& h, uint32_t& l) {
    __nv_bfloat16 ha = __float2bfloat16(a);
    __nv_bfloat16 hb = __float2bfloat16(b);
    __nv_bfloat16 la = __float2bfloat16(a - __bfloat162float(ha));
    __nv_bfloat16 lb = __float2bfloat16(b - __bfloat162float(hb));
    h = ((uint32_t)__bfloat16_as_ushort(hb) << 16) | (uint32_t)__bfloat16_as_ushort(ha);
    l = ((uint32_t)__bfloat16_as_ushort(lb) << 16) | (uint32_t)__bfloat16_as_ushort(la);
}

// ---- pre-pass: fp32 K,V -> bf16 hi/lo planes ----
__global__ __launch_bounds__(256)
void prep_kernel(const float* __restrict__ k, const float* __restrict__ v)
{
    const int idx = blockIdx.x * 256 + threadIdx.x;    // BH*NCTX*4 threads
    const size_t row = (size_t)(idx >> 2);             // token row (bh*NCTX + tok)
    const int ch = (idx & 3) * 16;                     // 16-elem chunk of DH
    const float4* kr = (const float4*)(k + row * DH + ch);
    const float4* vr = (const float4*)(v + row * DH + ch);
    const size_t ob = row * DH + ch;
#pragma unroll
    for (int j = 0; j < 4; ++j) {
        float4 a = kr[j];
        uint32_t h0, h1, l0, l1;
        split_pair(a.x, a.y, h0, l0);
        split_pair(a.z, a.w, h1, l1);
        *(uint2*)&gKV[0 * PLANE + ob + j * 4] = make_uint2(h0, h1);
        *(uint2*)&gKV[1 * PLANE + ob + j * 4] = make_uint2(l0, l1);
    }
#pragma unroll
    for (int j = 0; j < 4; ++j) {
        float4 a = vr[j];
        uint32_t h0, h1, l0, l1;
        split_pair(a.x, a.y, h0, l0);
        split_pair(a.z, a.w, h1, l1);
        *(uint2*)&gKV[2 * PLANE + ob + j * 4] = make_uint2(h0, h1);
        *(uint2*)&gKV[3 * PLANE + ob + j * 4] = make_uint2(l0, l1);
    }
}

// ---- main attention kernel: cp.async double-buffered, HMMA 3-term split ----
__global__ __launch_bounds__(NTH, 2)
void bsattn_mma_kernel(const float* __restrict__ q, const float* __restrict__ smp,
                       const int* __restrict__ rsv, const int* __restrict__ rev,
                       float* __restrict__ out)
{
    extern __shared__ __align__(16) uint16_t sm[];     // 2 stages x (Kh|Kl|Vh|Vl)
    __shared__ int red_lo, red_hi;

    const int tid  = threadIdx.x;
    const int wid  = tid >> 5;
    const int lane = tid & 31;
    const int qb   = gridDim.x - 1 - blockIdx.x;       // heavy q-tiles first
    const int bh   = blockIdx.y;
    const int q0   = qb * QM;

    const float sc = *smp;
    const float* qp = q   + ((size_t)bh * NCTX + q0) * DH;
    float*       op = out + ((size_t)bh * NCTX + q0) * DH;
    const size_t bhbase = (size_t)bh * NCTX;

    const int rloc = wid * 16 + (lane >> 2);
    const int rg0  = q0 + rloc;
    const int rs0 = rsv[rg0],     re0 = rev[rg0];
    const int rs1 = rsv[rg0 + 8], re1 = rev[rg0 + 8];

    if (tid == 0) { red_lo = 0x7fffffff; red_hi = 0; }
    __syncthreads();
    atomicMin(&red_lo, min(rs0, rs1));
    atomicMax(&red_hi, max(re0, re1));

    // ---- Preload Q as split A-fragments ----
    uint32_t qh[4][4], ql[4][4];
#pragma unroll
    for (int s = 0; s < 4; ++s)
#pragma unroll
        for (int f = 0; f < 4; ++f) {
            int row = wid * 16 + (lane >> 2) + (f & 1) * 8;
            int col = s * 16 + (lane & 3) * 2 + ((f >> 1) & 1) * 8;
            float2 a = *(const float2*)(qp + (size_t)row * DH + col);
            split_pair(a.x * sc, a.y * sc, qh[s][f], ql[s][f]);
        }

    __syncthreads();
    const int kv_lo = red_lo & ~(TN - 1);
    const int kv_hi = red_hi;

    const uint32_t base32 = smem_u32(sm);
    // ldmatrix per-lane offsets (stage-relative)
    const int rA = ((lane >> 4) << 3) + (lane & 7);
    const int cA = ((lane >> 3) & 1) << 3;
    const uint32_t khR = 0 * BUFB + 2 * (rA * KROW + cA);
    const uint32_t klR = 1 * BUFB + 2 * (rA * KROW + cA);
    const int rV = (((lane >> 3) & 1) << 3) + (lane & 7);
    const int cV = ((lane >> 4) & 1) << 3;
    const uint32_t vhR = 2 * BUFB + 2 * (rV * KROW + cV);
    const uint32_t vlR = 3 * BUFB + 2 * (rV * KROW + cV);

    float oacc[8][4];
#pragma unroll
    for (int t = 0; t < 8; ++t)
#pragma unroll
        for (int c = 0; c < 4; ++c) oacc[t][c] = 0.f;
    float l0 = 0.f, l1 = 0.f;

    // ---- async stage copy: 2048 x 16B chunks (4 buffers x 64 rows x 8) ----
#define ISSUE_STAGE(N0, STDST) do {                                            \
    const int _n0 = (N0); const uint32_t _std = (STDST);                       \
    _Pragma("unroll")                                                          \
    for (int _j = 0; _j < 8; ++_j) {                                           \
        int _c   = _j * 256 + tid;                                             \
        int _buf = _c >> 9;                                                    \
        int _r   = (_c >> 3) & 63;                                             \
        int _col = _c & 7;                                                     \
        const uint16_t* _src = gKV + (size_t)_buf * PLANE +                    \
                               (bhbase + _n0 + _r) * DH + _col * 8;            \
        uint32_t _dst = _std + _buf * BUFB + _r * (KROW * 2) + _col * 16;      \
        asm volatile("cp.async.cg.shared.global [%0], [%1], 16;"               \
                     :: "r"(_dst), "l"(_src));                                 \
    }                                                                          \
    asm volatile("cp.async.commit_group;" ::: "memory");                       \
} while (0)

    ISSUE_STAGE(kv_lo, base32);   // prologue: tile0 -> stage0

    for (int n0 = kv_lo, iter = 0; n0 < kv_hi; n0 += TN, ++iter) {
        const uint32_t stOff = (iter & 1) ? (uint32_t)STAGEB : 0u;
        const bool hasNext = (n0 + TN < kv_hi);
        if (hasNext) ISSUE_STAGE(n0 + TN, base32 + (stOff ^ STAGEB));
        if (hasNext) asm volatile("cp.async.wait_group 1;" ::: "memory");
        else         asm volatile("cp.async.wait_group 0;" ::: "memory");
        __syncthreads();

        const uint32_t khB = base32 + stOff + khR;
        const uint32_t klB = base32 + stOff + klR;
        const uint32_t vhB = base32 + stOff + vhR;
        const uint32_t vlB = base32 + stOff + vlR;

        // ---- GEMM1: S = Q K^T (hh + hl + lh) ----
        float sacc[8][4];
#pragma unroll
        for (int t = 0; t < 8; ++t)
#pragma unroll
            for (int c = 0; c < 4; ++c) sacc[t][c] = 0.f;

#pragma unroll
        for (int s = 0; s < 4; ++s)
#pragma unroll
            for (int p = 0; p < 4; ++p) {
                uint32_t bh4[4], bl4[4];
                const uint32_t off = (uint32_t)(p * 16 * KROW + s * 16) * 2;
                LDSM4(bh4, khB + off);
                LDSM4(bl4, klB + off);
                MMA(sacc[2 * p],     qh[s], bh4 + 0);
                MMA(sacc[2 * p + 1], qh[s], bh4 + 2);
                MMA(sacc[2 * p],     qh[s], bl4 + 0);
                MMA(sacc[2 * p + 1], qh[s], bl4 + 2);
                MMA(sacc[2 * p],     ql[s], bh4 + 0);
                MMA(sacc[2 * p + 1], ql[s], bh4 + 2);
            }

        // ---- fused softmax + GEMM2 per 16-col k-chunk ----
#pragma unroll
        for (int s = 0; s < 4; ++s) {
            const int c0a = n0 + (2 * s) * 8 + (lane & 3) * 2;
            const int c0b = c0a + 8;
            float pa0 = (c0a     >= rs0 && c0a     < re0) ? __expf(sacc[2*s][0])   : 0.f;
            float pa1 = (c0a + 1 >= rs0 && c0a + 1 < re0) ? __expf(sacc[2*s][1])   : 0.f;
            float pa2 = (c0a     >= rs1 && c0a     < re1) ? __expf(sacc[2*s][2])   : 0.f;
            float pa3 = (c0a + 1 >= rs1 && c0a + 1 < re1) ? __expf(sacc[2*s][3])   : 0.f;
            float pb0 = (c0b     >= rs0 && c0b     < re0) ? __expf(sacc[2*s+1][0]) : 0.f;
            float pb1 = (c0b + 1 >= rs0 && c0b + 1 < re0) ? __expf(sacc[2*s+1][1]) : 0.f;
            float pb2 = (c0b     >= rs1 && c0b     < re1) ? __expf(sacc[2*s+1][2]) : 0.f;
            float pb3 = (c0b + 1 >= rs1 && c0b + 1 < re1) ? __expf(sacc[2*s+1][3]) : 0.f;
            l0 += (pa0 + pa1) + (pb0 + pb1);
            l1 += (pa2 + pa3) + (pb2 + pb3);

            uint32_t pah[4], pal[4];
            split_pair(pa0, pa1, pah[0], pal[0]);
            split_pair(pa2, pa3, pah[1], pal[1]);
            split_pair(pb0, pb1, pah[2], pal[2]);
            split_pair(pb2, pb3, pah[3], pal[3]);

#pragma unroll
            for (int p = 0; p < 4; ++p) {
                uint32_t vh4[4], vl4[4];
                const uint32_t off = (uint32_t)(s * 16 * KROW + p * 16) * 2;
                LDSM4T(vh4, vhB + off);
                LDSM4T(vl4, vlB + off);
                MMA(oacc[2 * p],     pah, vh4 + 0);
                MMA(oacc[2 * p + 1], pah, vh4 + 2);
                MMA(oacc[2 * p],     pah, vl4 + 0);
                MMA(oacc[2 * p + 1], pah, vl4 + 2);
                MMA(oacc[2 * p],     pal, vh4 + 0);
                MMA(oacc[2 * p + 1], pal, vh4 + 2);
            }
        }
        __syncthreads();   // all warps done with stage before it is refilled
    }

    // ---- epilogue ----
    l0 += __shfl_xor_sync(0xffffffffu, l0, 1);
    l0 += __shfl_xor_sync(0xffffffffu, l0, 2);
    l1 += __shfl_xor_sync(0xffffffffu, l1, 1);
    l1 += __shfl_xor_sync(0xffffffffu, l1, 2);
    const float inv0 = 1.0f / l0;
    const float inv1 = 1.0f / l1;

    float* orow0 = op + (size_t)rloc * DH;
#pragma unroll
    for (int t = 0; t < 8; ++t) {
        const int col = t * 8 + (lane & 3) * 2;
        *(float2*)(orow0 + col)          = make_float2(oacc[t][0] * inv0, oacc[t][1] * inv0);
        *(float2*)(orow0 + 8 * DH + col) = make_float2(oacc[t][2] * inv1, oacc[t][3] * inv1);
    }
}

extern "C" void kernel_launch(void* const* d_in, const int* in_sizes, int n_in,
                              void* d_out, int out_size)
{
    const float* q   = (const float*)d_in[0];
    const float* k   = (const float*)d_in[1];
    const float* v   = (const float*)d_in[2];
    const float* smp = (const float*)d_in[3];
    const int* rsv   = (const int*)d_in[4];
    const int* rev   = (const int*)d_in[5];
    float* out = (float*)d_out;

    const int bh = in_sizes[0] / (NCTX * DH);   // 32

    // pre-pass: convert K,V to bf16 hi/lo planes
    prep_kernel<<<(bh * NCTX * 4) / 256, 256>>>(k, v);

    // main kernel: 2-stage dynamic smem
    static_assert(2 * STAGEB == 73728, "smem layout");
    cudaFuncSetAttribute(bsattn_mma_kernel,
                         cudaFuncAttributeMaxDynamicSharedMemorySize, 2 * STAGEB);
    dim3 grid(NCTX / QM, bh);
    bsattn_mma_kernel<<<grid, NTH, 2 * STAGEB>>>(q, smp, rsv, rev, out);
}

// round 11
// speedup vs baseline: 1.3918x; 1.3918x over previous
#include <cuda_runtime.h>
#include <cuda_bf16.h>
#include <cstdint>

#define NCTX 2048
#define DH   64
#define QM   128     // q rows per CTA
#define TN   64      // kv tokens per tile
#define NTH  256     // 8 warps
#define KROW 72      // smem row stride in bf16 elems (144B, ldmatrix conflict-free)
#define BUF_E   (TN * KROW)        // 4608 elems per buffer
#define STAGE_E (4 * BUF_E)        // elems per stage (Kh|Kl|Vh|Vl)
#define STAGE_B (STAGE_E * 2)      // 36864 bytes per stage
#define SMEM_TOT (2 * STAGE_B)     // 73728 bytes

static __device__ __forceinline__ uint32_t smem_u32(const void* p) {
    uint32_t a;
    asm("{ .reg .u64 t; cvta.to.shared.u64 t, %1; cvt.u32.u64 %0, t; }" : "=r"(a) : "l"(p));
    return a;
}
static __device__ __forceinline__ float ex2f(float x) {
    float r;
    asm("ex2.approx.f32 %0, %1;" : "=f"(r) : "f"(x));
    return r;
}

#define MMA(d, a, b) \
    asm volatile("mma.sync.aligned.m16n8k16.row.col.f32.bf16.bf16.f32 " \
        "{%0,%1,%2,%3}, {%4,%5,%6,%7}, {%8,%9}, {%0,%1,%2,%3};" \
        : "+f"((d)[0]), "+f"((d)[1]), "+f"((d)[2]), "+f"((d)[3]) \
        : "r"((a)[0]), "r"((a)[1]), "r"((a)[2]), "r"((a)[3]), "r"((b)[0]), "r"((b)[1]))

#define LDSM4(r, addr) \
    asm volatile("ldmatrix.sync.aligned.m8n8.x4.shared.b16 {%0,%1,%2,%3}, [%4];" \
        : "=r"((r)[0]), "=r"((r)[1]), "=r"((r)[2]), "=r"((r)[3]) : "r"(addr))

#define LDSM4T(r, addr) \
    asm volatile("ldmatrix.sync.aligned.m8n8.x4.trans.shared.b16 {%0,%1,%2,%3}, [%4];" \
        : "=r"((r)[0]), "=r"((r)[1]), "=r"((r)[2]), "=r"((r)[3]) : "r"(addr))

static __device__ __forceinline__ void split_pair(float a, float b, uint32_t& h, uint32_t& l) {
    __nv_bfloat16 ha = __float2bfloat16(a);
    __nv_bfloat16 hb = __float2bfloat16(b);
    __nv_bfloat16 la = __float2bfloat16(a - __bfloat162float(ha));
    __nv_bfloat16 lb = __float2bfloat16(b - __bfloat162float(hb));
    h = ((uint32_t)__bfloat16_as_ushort(hb) << 16) | (uint32_t)__bfloat16_as_ushort(ha);
    l = ((uint32_t)__bfloat16_as_ushort(lb) << 16) | (uint32_t)__bfloat16_as_ushort(la);
}

__global__ __launch_bounds__(NTH, 2)
void bsattn_mma_kernel(const float* __restrict__ q, const float* __restrict__ k,
                       const float* __restrict__ v, const float* __restrict__ smp,
                       const int* __restrict__ rsv, const int* __restrict__ rev,
                       float* __restrict__ out)
{
    extern __shared__ __align__(16) uint16_t sm[];   // 2 stages x (Kh|Kl|Vh|Vl)
    __shared__ int red_lo, red_hi;

    const int tid  = threadIdx.x;
    const int wid  = tid >> 5;
    const int lane = tid & 31;
    const int qb   = gridDim.x - 1 - blockIdx.x;     // heavy q-tiles first
    const int bh   = blockIdx.y;
    const int q0   = qb * QM;

    // fold log2e into Q scale: exp(s) = exp2(s * log2e)
    const float sc2 = (*smp) * 1.4426950408889634f;
    const float* qp = q   + ((size_t)bh * NCTX + q0) * DH;
    const float* kp = k   + (size_t)bh * NCTX * DH;
    const float* vp = v   + (size_t)bh * NCTX * DH;
    float*       op = out + ((size_t)bh * NCTX + q0) * DH;

    const int rloc = wid * 16 + (lane >> 2);
    const int rg0  = q0 + rloc;
    const int rs0 = rsv[rg0],     re0 = rev[rg0];
    const int rs1 = rsv[rg0 + 8], re1 = rev[rg0 + 8];

    if (tid == 0) { red_lo = 0x7fffffff; red_hi = 0; }
    __syncthreads();
    atomicMin(&red_lo, min(rs0, rs1));
    atomicMax(&red_hi, max(re0, re1));

    // ---- Preload Q as split A-fragments (pre-scaled by sc*log2e) ----
    uint32_t qh[4][4], ql[4][4];
#pragma unroll
    for (int s = 0; s < 4; ++s)
#pragma unroll
        for (int f = 0; f < 4; ++f) {
            int row = wid * 16 + (lane >> 2) + (f & 1) * 8;
            int col = s * 16 + (lane & 3) * 2 + ((f >> 1) & 1) * 8;
            float2 a = *(const float2*)(qp + (size_t)row * DH + col);
            split_pair(a.x * sc2, a.y * sc2, qh[s][f], ql[s][f]);
        }

    __syncthreads();
    const int kv_lo = red_lo & ~(TN - 1);
    const int kv_hi = red_hi;

    const uint32_t base32 = smem_u32(sm);
    // ldmatrix per-lane offsets (stage-relative, bytes)
    const int rA = ((lane >> 4) << 3) + (lane & 7);
    const int cA = ((lane >> 3) & 1) << 3;
    const uint32_t khR = 0 * BUF_E * 2 + 2 * (rA * KROW + cA);
    const uint32_t klR = 1 * BUF_E * 2 + 2 * (rA * KROW + cA);
    const int rV = (((lane >> 3) & 1) << 3) + (lane & 7);
    const int cV = ((lane >> 4) & 1) << 3;
    const uint32_t vhR = 2 * BUF_E * 2 + 2 * (rV * KROW + cV);
    const uint32_t vlR = 3 * BUF_E * 2 + 2 * (rV * KROW + cV);

    float oacc[8][4];
#pragma unroll
    for (int t = 0; t < 8; ++t)
#pragma unroll
        for (int c = 0; c < 4; ++c) oacc[t][c] = 0.f;
    float l0 = 0.f, l1 = 0.f;

    const int tok = tid >> 2;           // 0..63
    const int d0  = (tid & 3) * 16;     // 0,16,32,48
    const int sb  = tok * KROW + d0;    // smem elem offset within a buffer

    // ---- prologue: convert tile kv_lo into stage 0 ----
    {
        uint16_t* st = sm;              // stage 0
        const float* kb = kp + (size_t)(kv_lo + tok) * DH + d0;
        const float* vb = vp + (size_t)(kv_lo + tok) * DH + d0;
#pragma unroll
        for (int j = 0; j < 4; ++j) {
            float4 a = *(const float4*)(kb + j * 4);
            uint32_t h0, h1, lo0, lo1;
            split_pair(a.x, a.y, h0, lo0);
            split_pair(a.z, a.w, h1, lo1);
            *(uint2*)&st[0 * BUF_E + sb + j * 4] = make_uint2(h0, h1);
            *(uint2*)&st[1 * BUF_E + sb + j * 4] = make_uint2(lo0, lo1);
        }
#pragma unroll
        for (int j = 0; j < 4; ++j) {
            float4 a = *(const float4*)(vb + j * 4);
            uint32_t h0, h1, lo0, lo1;
            split_pair(a.x, a.y, h0, lo0);
            split_pair(a.z, a.w, h1, lo1);
            *(uint2*)&st[2 * BUF_E + sb + j * 4] = make_uint2(h0, h1);
            *(uint2*)&st[3 * BUF_E + sb + j * 4] = make_uint2(lo0, lo1);
        }
    }

    for (int n0 = kv_lo, iter = 0; n0 < kv_hi; n0 += TN, ++iter) {
        __syncthreads();   // stage(cur) written; previous reads of stage(nxt) done
        const uint32_t stB = (iter & 1) ? (uint32_t)STAGE_B : 0u;
        uint16_t* stN = sm + ((iter & 1) ? 0 : STAGE_E);   // next stage base
        const bool hasNext = (n0 + TN < kv_hi);

        // issue K LDGs for next tile (latency hidden under GEMM1)
        float4 kst[4];
        if (hasNext) {
            const float* kb = kp + (size_t)(n0 + TN + tok) * DH + d0;
#pragma unroll
            for (int j = 0; j < 4; ++j) kst[j] = *(const float4*)(kb + j * 4);
        }

        const uint32_t khB = base32 + stB + khR;
        const uint32_t klB = base32 + stB + klR;
        const uint32_t vhB = base32 + stB + vhR;
        const uint32_t vlB = base32 + stB + vlR;

        // ---- GEMM1: S = Q K^T (hh + hl + lh) ----
        float sacc[8][4];
#pragma unroll
        for (int t = 0; t < 8; ++t)
#pragma unroll
            for (int c = 0; c < 4; ++c) sacc[t][c] = 0.f;

#pragma unroll
        for (int s = 0; s < 4; ++s)
#pragma unroll
            for (int p = 0; p < 4; ++p) {
                uint32_t bh4[4], bl4[4];
                const uint32_t off = (uint32_t)(p * 16 * KROW + s * 16) * 2;
                LDSM4(bh4, khB + off);
                LDSM4(bl4, klB + off);
                MMA(sacc[2 * p],     qh[s], bh4 + 0);
                MMA(sacc[2 * p + 1], qh[s], bh4 + 2);
                MMA(sacc[2 * p],     qh[s], bl4 + 0);
                MMA(sacc[2 * p + 1], qh[s], bl4 + 2);
                MMA(sacc[2 * p],     ql[s], bh4 + 0);
                MMA(sacc[2 * p + 1], ql[s], bh4 + 2);
            }

        // convert + store K(next); then issue V LDGs (hidden under GEMM2)
        float4 vst[4];
        if (hasNext) {
#pragma unroll
            for (int j = 0; j < 4; ++j) {
                uint32_t h0, h1, lo0, lo1;
                split_pair(kst[j].x, kst[j].y, h0, lo0);
                split_pair(kst[j].z, kst[j].w, h1, lo1);
                *(uint2*)&stN[0 * BUF_E + sb + j * 4] = make_uint2(h0, h1);
                *(uint2*)&stN[1 * BUF_E + sb + j * 4] = make_uint2(lo0, lo1);
            }
            const float* vb = vp + (size_t)(n0 + TN + tok) * DH + d0;
#pragma unroll
            for (int j = 0; j < 4; ++j) vst[j] = *(const float4*)(vb + j * 4);
        }

        // ---- fused softmax + GEMM2 per 16-col k-chunk ----
#pragma unroll
        for (int s = 0; s < 4; ++s) {
            const int c0a = n0 + (2 * s) * 8 + (lane & 3) * 2;
            const int c0b = c0a + 8;
            float pa0 = (c0a     >= rs0 && c0a     < re0) ? ex2f(sacc[2*s][0])   : 0.f;
            float pa1 = (c0a + 1 >= rs0 && c0a + 1 < re0) ? ex2f(sacc[2*s][1])   : 0.f;
            float pa2 = (c0a     >= rs1 && c0a     < re1) ? ex2f(sacc[2*s][2])   : 0.f;
            float pa3 = (c0a + 1 >= rs1 && c0a + 1 < re1) ? ex2f(sacc[2*s][3])   : 0.f;
            float pb0 = (c0b     >= rs0 && c0b     < re0) ? ex2f(sacc[2*s+1][0]) : 0.f;
            float pb1 = (c0b + 1 >= rs0 && c0b + 1 < re0) ? ex2f(sacc[2*s+1][1]) : 0.f;
            float pb2 = (c0b     >= rs1 && c0b     < re1) ? ex2f(sacc[2*s+1][2]) : 0.f;
            float pb3 = (c0b + 1 >= rs1 && c0b + 1 < re1) ? ex2f(sacc[2*s+1][3]) : 0.f;
            l0 += (pa0 + pa1) + (pb0 + pb1);
            l1 += (pa2 + pa3) + (pb2 + pb3);

            uint32_t pah[4], pal[4];
            split_pair(pa0, pa1, pah[0], pal[0]);
            split_pair(pa2, pa3, pah[1], pal[1]);
            split_pair(pb0, pb1, pah[2], pal[2]);
            split_pair(pb2, pb3, pah[3], pal[3]);

#pragma unroll
            for (int p = 0; p < 4; ++p) {
                uint32_t vh4[4], vl4[4];
                const uint32_t off = (uint32_t)(s * 16 * KROW + p * 16) * 2;
                LDSM4T(vh4, vhB + off);
                LDSM4T(vl4, vlB + off);
                MMA(oacc[2 * p],     pah, vh4 + 0);
                MMA(oacc[2 * p + 1], pah, vh4 + 2);
                MMA(oacc[2 * p],     pah, vl4 + 0);
                MMA(oacc[2 * p + 1], pah, vl4 + 2);
                MMA(oacc[2 * p],     pal, vh4 + 0);
                MMA(oacc[2 * p + 1], pal, vh4 + 2);
            }
        }

        // convert + store V(next)
        if (hasNext) {
#pragma unroll
            for (int j = 0; j < 4; ++j) {
                uint32_t h0, h1, lo0, lo1;
                split_pair(vst[j].x, vst[j].y, h0, lo0);
                split_pair(vst[j].z, vst[j].w, h1, lo1);
                *(uint2*)&stN[2 * BUF_E + sb + j * 4] = make_uint2(h0, h1);
                *(uint2*)&stN[3 * BUF_E + sb + j * 4] = make_uint2(lo0, lo1);
            }
        }
    }

    // ---- epilogue: reduce l across the quad, normalize, store ----
    l0 += __shfl_xor_sync(0xffffffffu, l0, 1);
    l0 += __shfl_xor_sync(0xffffffffu, l0, 2);
    l1 += __shfl_xor_sync(0xffffffffu, l1, 1);
    l1 += __shfl_xor_sync(0xffffffffu, l1, 2);
    const float inv0 = 1.0f / l0;
    const float inv1 = 1.0f / l1;

    float* orow0 = op + (size_t)rloc * DH;
#pragma unroll
    for (int t = 0; t < 8; ++t) {
        const int col = t * 8 + (lane & 3) * 2;
        *(float2*)(orow0 + col)          = make_float2(oacc[t][0] * inv0, oacc[t][1] * inv0);
        *(float2*)(orow0 + 8 * DH + col) = make_float2(oacc[t][2] * inv1, oacc[t][3] * inv1);
    }
}

extern "C" void kernel_launch(void* const* d_in, const int* in_sizes, int n_in,
                              void* d_out, int out_size)
{
    const float* q   = (const float*)d_in[0];
    const float* k   = (const float*)d_in[1];
    const float* v   = (const float*)d_in[2];
    const float* smp = (const float*)d_in[3];
    const int* rsv   = (const int*)d_in[4];
    const int* rev   = (const int*)d_in[5];
    float* out = (float*)d_out;

    const int bh = in_sizes[0] / (NCTX * DH);   // B*H = 32
    cudaFuncSetAttribute(bsattn_mma_kernel,
                         cudaFuncAttributeMaxDynamicSharedMemorySize, SMEM_TOT);
    dim3 grid(NCTX / QM, bh);
    bsattn_mma_kernel<<<grid, NTH, SMEM_TOT>>>(q, k, v, smp, rsv, rev, out);
}

// round 12
// speedup vs baseline: 1.8120x; 1.3019x over previous
#include <cuda_runtime.h>
#include <cuda_bf16.h>
#include <cstdint>

#define NCTX 2048
#define DH   64
#define QM   128     // q rows per CTA
#define TN   64      // kv tokens per tile
#define NTH  256     // 8 warps
#define KROW 72      // smem row stride in bf16 elems (144B, ldmatrix conflict-free)
#define BUF_E   (TN * KROW)        // 4608 elems per buffer
#define STAGE_E (4 * BUF_E)        // elems per stage (Kh|Kl|Vh|Vl)
#define STAGE_B (STAGE_E * 2)      // 36864 bytes per stage
#define SMEM_TOT (2 * STAGE_B)     // 73728 bytes

static __device__ __forceinline__ uint32_t smem_u32(const void* p) {
    uint32_t a;
    asm("{ .reg .u64 t; cvta.to.shared.u64 t, %1; cvt.u32.u64 %0, t; }" : "=r"(a) : "l"(p));
    return a;
}
static __device__ __forceinline__ float ex2f(float x) {
    float r;
    asm("ex2.approx.f32 %0, %1;" : "=f"(r) : "f"(x));
    return r;
}

#define MMA(d, a, b) \
    asm volatile("mma.sync.aligned.m16n8k16.row.col.f32.bf16.bf16.f32 " \
        "{%0,%1,%2,%3}, {%4,%5,%6,%7}, {%8,%9}, {%0,%1,%2,%3};" \
        : "+f"((d)[0]), "+f"((d)[1]), "+f"((d)[2]), "+f"((d)[3]) \
        : "r"((a)[0]), "r"((a)[1]), "r"((a)[2]), "r"((a)[3]), "r"((b)[0]), "r"((b)[1]))

#define LDSM4(r, addr) \
    asm volatile("ldmatrix.sync.aligned.m8n8.x4.shared.b16 {%0,%1,%2,%3}, [%4];" \
        : "=r"((r)[0]), "=r"((r)[1]), "=r"((r)[2]), "=r"((r)[3]) : "r"(addr))

#define LDSM4T(r, addr) \
    asm volatile("ldmatrix.sync.aligned.m8n8.x4.trans.shared.b16 {%0,%1,%2,%3}, [%4];" \
        : "=r"((r)[0]), "=r"((r)[1]), "=r"((r)[2]), "=r"((r)[3]) : "r"(addr))

// fast split: packed cvt + bit-reconstructed hi halves (bit-identical to scalar rn)
static __device__ __forceinline__ void split_pair(float a, float b, uint32_t& h, uint32_t& l) {
    asm("cvt.rn.bf16x2.f32 %0, %1, %2;" : "=r"(h) : "f"(b), "f"(a));   // lo=cvt(a), hi=cvt(b)
    float fa = __uint_as_float(h << 16);
    float fb = __uint_as_float(h & 0xffff0000u);
    float ra = a - fa;
    float rb = b - fb;
    asm("cvt.rn.bf16x2.f32 %0, %1, %2;" : "=r"(l) : "f"(rb), "f"(ra));
}

__global__ __launch_bounds__(NTH, 2)
void bsattn_mma_kernel(const float* __restrict__ q, const float* __restrict__ k,
                       const float* __restrict__ v, const float* __restrict__ smp,
                       const int* __restrict__ rsv, const int* __restrict__ rev,
                       float* __restrict__ out)
{
    extern __shared__ __align__(16) uint16_t sm[];   // 2 stages x (Kh|Kl|Vh|Vl)
    __shared__ int red_lo, red_hi;

    const int tid  = threadIdx.x;
    const int wid  = tid >> 5;
    const int lane = tid & 31;
    const int qb   = gridDim.x - 1 - blockIdx.x;     // heavy q-tiles first
    const int bh   = blockIdx.y;
    const int q0   = qb * QM;

    // fold log2e into Q scale: exp(s) = exp2(s * log2e)
    const float sc2 = (*smp) * 1.4426950408889634f;
    const float* qp = q   + ((size_t)bh * NCTX + q0) * DH;
    const float* kp = k   + (size_t)bh * NCTX * DH;
    const float* vp = v   + (size_t)bh * NCTX * DH;
    float*       op = out + ((size_t)bh * NCTX + q0) * DH;

    const int rloc = wid * 16 + (lane >> 2);
    const int rg0  = q0 + rloc;
    const int rs0 = rsv[rg0],     re0 = rev[rg0];
    const int rs1 = rsv[rg0 + 8], re1 = rev[rg0 + 8];

    if (tid == 0) { red_lo = 0x7fffffff; red_hi = 0; }
    __syncthreads();
    atomicMin(&red_lo, min(rs0, rs1));
    atomicMax(&red_hi, max(re0, re1));

    // ---- Preload Q as split A-fragments (pre-scaled by sc*log2e) ----
    uint32_t qh[4][4], ql[4][4];
#pragma unroll
    for (int s = 0; s < 4; ++s)
#pragma unroll
        for (int f = 0; f < 4; ++f) {
            int row = wid * 16 + (lane >> 2) + (f & 1) * 8;
            int col = s * 16 + (lane & 3) * 2 + ((f >> 1) & 1) * 8;
            float2 a = *(const float2*)(qp + (size_t)row * DH + col);
            split_pair(a.x * sc2, a.y * sc2, qh[s][f], ql[s][f]);
        }

    __syncthreads();
    const int kv_lo = red_lo & ~(TN - 1);
    const int kv_hi = red_hi;

    const uint32_t base32 = smem_u32(sm);
    // ldmatrix per-lane offsets (stage-relative, bytes)
    const int rA = ((lane >> 4) << 3) + (lane & 7);
    const int cA = ((lane >> 3) & 1) << 3;
    const uint32_t khR = 0 * BUF_E * 2 + 2 * (rA * KROW + cA);
    const uint32_t klR = 1 * BUF_E * 2 + 2 * (rA * KROW + cA);
    const int rV = (((lane >> 3) & 1) << 3) + (lane & 7);
    const int cV = ((lane >> 4) & 1) << 3;
    const uint32_t vhR = 2 * BUF_E * 2 + 2 * (rV * KROW + cV);
    const uint32_t vlR = 3 * BUF_E * 2 + 2 * (rV * KROW + cV);

    float oacc[8][4];
#pragma unroll
    for (int t = 0; t < 8; ++t)
#pragma unroll
        for (int c = 0; c < 4; ++c) oacc[t][c] = 0.f;
    float l0 = 0.f, l1 = 0.f;

    const int tok = tid >> 2;           // 0..63
    const int d0  = (tid & 3) * 16;     // 0,16,32,48
    const int sb  = tok * KROW + d0;    // smem elem offset within a buffer

    for (int n0 = kv_lo, iter = 0; n0 < kv_hi; n0 += TN, ++iter) {
        uint16_t* st = sm + (iter & 1) * STAGE_E;
        const uint32_t stB = base32 + (iter & 1) * STAGE_B;

        // ---- convert tile n0 into stage (no barrier before: prev reads were
        //      of the other stage; 2-ago reads finished before last sync) ----
        {
            const float* kb = kp + (size_t)(n0 + tok) * DH + d0;
            const float* vb = vp + (size_t)(n0 + tok) * DH + d0;
#pragma unroll
            for (int j = 0; j < 4; ++j) {
                float4 a = *(const float4*)(kb + j * 4);
                uint32_t h0, h1, lo0, lo1;
                split_pair(a.x, a.y, h0, lo0);
                split_pair(a.z, a.w, h1, lo1);
                *(uint2*)&st[0 * BUF_E + sb + j * 4] = make_uint2(h0, h1);
                *(uint2*)&st[1 * BUF_E + sb + j * 4] = make_uint2(lo0, lo1);
            }
#pragma unroll
            for (int j = 0; j < 4; ++j) {
                float4 a = *(const float4*)(vb + j * 4);
                uint32_t h0, h1, lo0, lo1;
                split_pair(a.x, a.y, h0, lo0);
                split_pair(a.z, a.w, h1, lo1);
                *(uint2*)&st[2 * BUF_E + sb + j * 4] = make_uint2(h0, h1);
                *(uint2*)&st[3 * BUF_E + sb + j * 4] = make_uint2(lo0, lo1);
            }
        }
        __syncthreads();    // single barrier per tile: stage written -> readable

        const uint32_t khB = stB + khR;
        const uint32_t klB = stB + klR;
        const uint32_t vhB = stB + vhR;
        const uint32_t vlB = stB + vlR;

        // ---- GEMM1: S = Q K^T (hh+hl+lh), p-pair blocked for RAW spacing ----
        float sacc[8][4];
#pragma unroll
        for (int t = 0; t < 8; ++t)
#pragma unroll
            for (int c = 0; c < 4; ++c) sacc[t][c] = 0.f;

#pragma unroll
        for (int s = 0; s < 4; ++s)
#pragma unroll
            for (int pp = 0; pp < 2; ++pp) {
                uint32_t bh0[4], bl0[4], bh1[4], bl1[4];
                const uint32_t off0 = (uint32_t)((2 * pp + 0) * 16 * KROW + s * 16) * 2;
                const uint32_t off1 = (uint32_t)((2 * pp + 1) * 16 * KROW + s * 16) * 2;
                LDSM4(bh0, khB + off0);
                LDSM4(bh1, khB + off1);
                LDSM4(bl0, klB + off0);
                LDSM4(bl1, klB + off1);
                float* d0_ = sacc[4 * pp + 0];
                float* d1_ = sacc[4 * pp + 1];
                float* d2_ = sacc[4 * pp + 2];
                float* d3_ = sacc[4 * pp + 3];
                MMA(d0_, qh[s], bh0 + 0); MMA(d1_, qh[s], bh0 + 2);
                MMA(d2_, qh[s], bh1 + 0); MMA(d3_, qh[s], bh1 + 2);
                MMA(d0_, qh[s], bl0 + 0); MMA(d1_, qh[s], bl0 + 2);
                MMA(d2_, qh[s], bl1 + 0); MMA(d3_, qh[s], bl1 + 2);
                MMA(d0_, ql[s], bh0 + 0); MMA(d1_, ql[s], bh0 + 2);
                MMA(d2_, ql[s], bh1 + 0); MMA(d3_, ql[s], bh1 + 2);
            }

        // ---- fused softmax + GEMM2 per 16-col k-chunk, p-pair blocked ----
        const bool fullT = (rs0 <= n0) && (rs1 <= n0) &&
                           (re0 >= n0 + TN) && (re1 >= n0 + TN);
#pragma unroll
        for (int s = 0; s < 4; ++s) {
            float pa0, pa1, pa2, pa3, pb0, pb1, pb2, pb3;
            if (fullT) {
                pa0 = ex2f(sacc[2*s][0]);   pa1 = ex2f(sacc[2*s][1]);
                pa2 = ex2f(sacc[2*s][2]);   pa3 = ex2f(sacc[2*s][3]);
                pb0 = ex2f(sacc[2*s+1][0]); pb1 = ex2f(sacc[2*s+1][1]);
                pb2 = ex2f(sacc[2*s+1][2]); pb3 = ex2f(sacc[2*s+1][3]);
            } else {
                const int c0a = n0 + (2 * s) * 8 + (lane & 3) * 2;
                const int c0b = c0a + 8;
                pa0 = (c0a     >= rs0 && c0a     < re0) ? ex2f(sacc[2*s][0])   : 0.f;
                pa1 = (c0a + 1 >= rs0 && c0a + 1 < re0) ? ex2f(sacc[2*s][1])   : 0.f;
                pa2 = (c0a     >= rs1 && c0a     < re1) ? ex2f(sacc[2*s][2])   : 0.f;
                pa3 = (c0a + 1 >= rs1 && c0a + 1 < re1) ? ex2f(sacc[2*s][3])   : 0.f;
                pb0 = (c0b     >= rs0 && c0b     < re0) ? ex2f(sacc[2*s+1][0]) : 0.f;
                pb1 = (c0b + 1 >= rs0 && c0b + 1 < re0) ? ex2f(sacc[2*s+1][1]) : 0.f;
                pb2 = (c0b     >= rs1 && c0b     < re1) ? ex2f(sacc[2*s+1][2]) : 0.f;
                pb3 = (c0b + 1 >= rs1 && c0b + 1 < re1) ? ex2f(sacc[2*s+1][3]) : 0.f;
            }
            l0 += (pa0 + pa1) + (pb0 + pb1);
            l1 += (pa2 + pa3) + (pb2 + pb3);

            uint32_t pah[4], pal[4];
            split_pair(pa0, pa1, pah[0], pal[0]);
            split_pair(pa2, pa3, pah[1], pal[1]);
            split_pair(pb0, pb1, pah[2], pal[2]);
            split_pair(pb2, pb3, pah[3], pal[3]);

#pragma unroll
            for (int pp = 0; pp < 2; ++pp) {
                uint32_t vh0[4], vl0[4], vh1[4], vl1[4];
                const uint32_t off0 = (uint32_t)(s * 16 * KROW + (2 * pp + 0) * 16) * 2;
                const uint32_t off1 = (uint32_t)(s * 16 * KROW + (2 * pp + 1) * 16) * 2;
                LDSM4T(vh0, vhB + off0);
                LDSM4T(vh1, vhB + off1);
                LDSM4T(vl0, vlB + off0);
                LDSM4T(vl1, vlB + off1);
                float* o0_ = oacc[4 * pp + 0];
                float* o1_ = oacc[4 * pp + 1];
                float* o2_ = oacc[4 * pp + 2];
                float* o3_ = oacc[4 * pp + 3];
                MMA(o0_, pah, vh0 + 0); MMA(o1_, pah, vh0 + 2);
                MMA(o2_, pah, vh1 + 0); MMA(o3_, pah, vh1 + 2);
                MMA(o0_, pah, vl0 + 0); MMA(o1_, pah, vl0 + 2);
                MMA(o2_, pah, vl1 + 0); MMA(o3_, pah, vl1 + 2);
                MMA(o0_, pal, vh0 + 0); MMA(o1_, pal, vh0 + 2);
                MMA(o2_, pal, vh1 + 0); MMA(o3_, pal, vh1 + 2);
            }
        }
    }

    // ---- epilogue: reduce l across the quad, normalize, store ----
    l0 += __shfl_xor_sync(0xffffffffu, l0, 1);
    l0 += __shfl_xor_sync(0xffffffffu, l0, 2);
    l1 += __shfl_xor_sync(0xffffffffu, l1, 1);
    l1 += __shfl_xor_sync(0xffffffffu, l1, 2);
    const float inv0 = 1.0f / l0;
    const float inv1 = 1.0f / l1;

    float* orow0 = op + (size_t)rloc * DH;
#pragma unroll
    for (int t = 0; t < 8; ++t) {
        const int col = t * 8 + (lane & 3) * 2;
        *(float2*)(orow0 + col)          = make_float2(oacc[t][0] * inv0, oacc[t][1] * inv0);
        *(float2*)(orow0 + 8 * DH + col) = make_float2(oacc[t][2] * inv1, oacc[t][3] * inv1);
    }
}

extern "C" void kernel_launch(void* const* d_in, const int* in_sizes, int n_in,
                              void* d_out, int out_size)
{
    const float* q   = (const float*)d_in[0];
    const float* k   = (const float*)d_in[1];
    const float* v   = (const float*)d_in[2];
    const float* smp = (const float*)d_in[3];
    const int* rsv   = (const int*)d_in[4];
    const int* rev   = (const int*)d_in[5];
    float* out = (float*)d_out;

    const int bh = in_sizes[0] / (NCTX * DH);   // B*H = 32
    cudaFuncSetAttribute(bsattn_mma_kernel,
                         cudaFuncAttributeMaxDynamicSharedMemorySize, SMEM_TOT);
    dim3 grid(NCTX / QM, bh);
    bsattn_mma_kernel<<<grid, NTH, SMEM_TOT>>>(q, k, v, smp, rsv, rev, out);
}

// round 15
// speedup vs baseline: 2.5217x; 1.3917x over previous
#include <cuda_runtime.h>
#include <cuda_bf16.h>
#include <cstdint>

#define NCTX 2048
#define DH   64
#define QM   128     // q rows per CTA
#define TN   64      // kv tokens per tile
#define NTH  256     // 8 warps
#define KROW 72      // smem row stride in bf16/fp16 elems (144B, ldmatrix conflict-free)
#define BUF_E   (TN * KROW)        // 4608 elems per buffer
#define STAGE_E (3 * BUF_E)        // elems per stage (Kh|Kl|Vf16)
#define STAGE_B (STAGE_E * 2)      // 27648 bytes per stage
#define SMEM_TOT (2 * STAGE_B)     // 55296 bytes

static __device__ __forceinline__ uint32_t smem_u32(const void* p) {
    uint32_t a;
    asm("{ .reg .u64 t; cvta.to.shared.u64 t, %1; cvt.u32.u64 %0, t; }" : "=r"(a) : "l"(p));
    return a;
}
static __device__ __forceinline__ float ex2f(float x) {
    float r;
    asm("ex2.approx.f32 %0, %1;" : "=f"(r) : "f"(x));
    return r;
}

// bf16 MMA (GEMM1): D += A * B
#define MMA(d, a, b) \
    asm volatile("mma.sync.aligned.m16n8k16.row.col.f32.bf16.bf16.f32 " \
        "{%0,%1,%2,%3}, {%4,%5,%6,%7}, {%8,%9}, {%0,%1,%2,%3};" \
        : "+f"((d)[0]), "+f"((d)[1]), "+f"((d)[2]), "+f"((d)[3]) \
        : "r"((a)[0]), "r"((a)[1]), "r"((a)[2]), "r"((a)[3]), "r"((b)[0]), "r"((b)[1]))

// fp16 MMA (GEMM2): D += A * B
#define MMAH(d, a, b) \
    asm volatile("mma.sync.aligned.m16n8k16.row.col.f32.f16.f16.f32 " \
        "{%0,%1,%2,%3}, {%4,%5,%6,%7}, {%8,%9}, {%0,%1,%2,%3};" \
        : "+f"((d)[0]), "+f"((d)[1]), "+f"((d)[2]), "+f"((d)[3]) \
        : "r"((a)[0]), "r"((a)[1]), "r"((a)[2]), "r"((a)[3]), "r"((b)[0]), "r"((b)[1]))

#define LDSM4(r, addr) \
    asm volatile("ldmatrix.sync.aligned.m8n8.x4.shared.b16 {%0,%1,%2,%3}, [%4];" \
        : "=r"((r)[0]), "=r"((r)[1]), "=r"((r)[2]), "=r"((r)[3]) : "r"(addr))

#define LDSM4T(r, addr) \
    asm volatile("ldmatrix.sync.aligned.m8n8.x4.trans.shared.b16 {%0,%1,%2,%3}, [%4];" \
        : "=r"((r)[0]), "=r"((r)[1]), "=r"((r)[2]), "=r"((r)[3]) : "r"(addr))

// fast bf16 split: packed cvt + bit-reconstructed hi halves
static __device__ __forceinline__ void split_pair(float a, float b, uint32_t& h, uint32_t& l) {
    asm("cvt.rn.bf16x2.f32 %0, %1, %2;" : "=r"(h) : "f"(b), "f"(a));   // lo=cvt(a), hi=cvt(b)
    float fa = __uint_as_float(h << 16);
    float fb = __uint_as_float(h & 0xffff0000u);
    float ra = a - fa;
    float rb = b - fb;
    asm("cvt.rn.bf16x2.f32 %0, %1, %2;" : "=r"(l) : "f"(rb), "f"(ra));
}
// pack two f32 -> f16x2 (lo=a, hi=b)
static __device__ __forceinline__ uint32_t pack_h2(float a, float b) {
    uint32_t r;
    asm("cvt.rn.f16x2.f32 %0, %1, %2;" : "=r"(r) : "f"(b), "f"(a));
    return r;
}

__global__ __launch_bounds__(NTH, 2)
void bsattn_mma_kernel(const float* __restrict__ q, const float* __restrict__ k,
                       const float* __restrict__ v, const float* __restrict__ smp,
                       const int* __restrict__ rsv, const int* __restrict__ rev,
                       float* __restrict__ out)
{
    extern __shared__ __align__(16) uint16_t sm[];   // 2 stages x (Kh|Kl|Vf16)
    __shared__ int red_lo, red_hi;

    const int tid  = threadIdx.x;
    const int wid  = tid >> 5;
    const int lane = tid & 31;
    const int qb   = gridDim.x - 1 - blockIdx.x;     // heavy q-tiles first
    const int bh   = blockIdx.y;
    const int q0   = qb * QM;

    // fold log2e into Q scale: exp(s) = exp2(s * log2e)
    const float sc2 = (*smp) * 1.4426950408889634f;
    const float* qp = q   + ((size_t)bh * NCTX + q0) * DH;
    const float* kp = k   + (size_t)bh * NCTX * DH;
    const float* vp = v   + (size_t)bh * NCTX * DH;
    float*       op = out + ((size_t)bh * NCTX + q0) * DH;

    const int rloc = wid * 16 + (lane >> 2);
    const int rg0  = q0 + rloc;
    const int rs0 = rsv[rg0],     re0 = rev[rg0];
    const int rs1 = rsv[rg0 + 8], re1 = rev[rg0 + 8];

    if (tid == 0) { red_lo = 0x7fffffff; red_hi = 0; }
    __syncthreads();
    atomicMin(&red_lo, min(rs0, rs1));
    atomicMax(&red_hi, max(re0, re1));

    // ---- Preload Q as split A-fragments (pre-scaled by sc*log2e) ----
    uint32_t qh[4][4], ql[4][4];
#pragma unroll
    for (int s = 0; s < 4; ++s)
#pragma unroll
        for (int f = 0; f < 4; ++f) {
            int row = wid * 16 + (lane >> 2) + (f & 1) * 8;
            int col = s * 16 + (lane & 3) * 2 + ((f >> 1) & 1) * 8;
            float2 a = *(const float2*)(qp + (size_t)row * DH + col);
            split_pair(a.x * sc2, a.y * sc2, qh[s][f], ql[s][f]);
        }

    __syncthreads();
    const int kv_lo = red_lo & ~(TN - 1);
    const int kv_hi = red_hi;

    const uint32_t base32 = smem_u32(sm);
    // ldmatrix per-lane offsets (stage-relative, bytes)
    const int rA = ((lane >> 4) << 3) + (lane & 7);
    const int cA = ((lane >> 3) & 1) << 3;
    const uint32_t khR = 0 * BUF_E * 2 + 2 * (rA * KROW + cA);
    const uint32_t klR = 1 * BUF_E * 2 + 2 * (rA * KROW + cA);
    const int rV = (((lane >> 3) & 1) << 3) + (lane & 7);
    const int cV = ((lane >> 4) & 1) << 3;
    const uint32_t vfR = 2 * BUF_E * 2 + 2 * (rV * KROW + cV);

    float oacc[8][4];
#pragma unroll
    for (int t = 0; t < 8; ++t)
#pragma unroll
        for (int c = 0; c < 4; ++c) oacc[t][c] = 0.f;
    float l0 = 0.f, l1 = 0.f;

    const int tok = tid >> 2;           // 0..63
    const int d0  = (tid & 3) * 16;     // 0,16,32,48
    const int sb  = tok * KROW + d0;    // smem elem offset within a buffer

    for (int n0 = kv_lo, iter = 0; n0 < kv_hi; n0 += TN, ++iter) {
        uint16_t* st = sm + (iter & 1) * STAGE_E;
        const uint32_t stB = base32 + (iter & 1) * STAGE_B;

        // ---- convert tile n0 into stage ----
        {
            const float* kb = kp + (size_t)(n0 + tok) * DH + d0;
            const float* vb = vp + (size_t)(n0 + tok) * DH + d0;
#pragma unroll
            for (int j = 0; j < 4; ++j) {
                float4 a = *(const float4*)(kb + j * 4);
                uint32_t h0, h1, lo0, lo1;
                split_pair(a.x, a.y, h0, lo0);
                split_pair(a.z, a.w, h1, lo1);
                *(uint2*)&st[0 * BUF_E + sb + j * 4] = make_uint2(h0, h1);
                *(uint2*)&st[1 * BUF_E + sb + j * 4] = make_uint2(lo0, lo1);
            }
#pragma unroll
            for (int j = 0; j < 4; ++j) {
                float4 a = *(const float4*)(vb + j * 4);
                *(uint2*)&st[2 * BUF_E + sb + j * 4] =
                    make_uint2(pack_h2(a.x, a.y), pack_h2(a.z, a.w));
            }
        }
        __syncthreads();    // single barrier per tile

        const uint32_t khB = stB + khR;
        const uint32_t klB = stB + klR;
        const uint32_t vfB = stB + vfR;

        // ---- GEMM1: S = Q K^T (hh+hl+lh bf16), p-pair blocked ----
        float sacc[8][4];
#pragma unroll
        for (int t = 0; t < 8; ++t)
#pragma unroll
            for (int c = 0; c < 4; ++c) sacc[t][c] = 0.f;

#pragma unroll
        for (int s = 0; s < 4; ++s)
#pragma unroll
            for (int pp = 0; pp < 2; ++pp) {
                uint32_t bh0[4], bl0[4], bh1[4], bl1[4];
                const uint32_t off0 = (uint32_t)((2 * pp + 0) * 16 * KROW + s * 16) * 2;
                const uint32_t off1 = (uint32_t)((2 * pp + 1) * 16 * KROW + s * 16) * 2;
                LDSM4(bh0, khB + off0);
                LDSM4(bh1, khB + off1);
                LDSM4(bl0, klB + off0);
                LDSM4(bl1, klB + off1);
                float* d0_ = sacc[4 * pp + 0];
                float* d1_ = sacc[4 * pp + 1];
                float* d2_ = sacc[4 * pp + 2];
                float* d3_ = sacc[4 * pp + 3];
                MMA(d0_, qh[s], bh0 + 0); MMA(d1_, qh[s], bh0 + 2);
                MMA(d2_, qh[s], bh1 + 0); MMA(d3_, qh[s], bh1 + 2);
                MMA(d0_, qh[s], bl0 + 0); MMA(d1_, qh[s], bl0 + 2);
                MMA(d2_, qh[s], bl1 + 0); MMA(d3_, qh[s], bl1 + 2);
                MMA(d0_, ql[s], bh0 + 0); MMA(d1_, ql[s], bh0 + 2);
                MMA(d2_, ql[s], bh1 + 0); MMA(d3_, ql[s], bh1 + 2);
            }

        // ---- fused softmax + GEMM2 (single-term fp16) per 16-col k-chunk ----
        const bool fullT = (rs0 <= n0) && (rs1 <= n0) &&
                           (re0 >= n0 + TN) && (re1 >= n0 + TN);
#pragma unroll
        for (int s = 0; s < 4; ++s) {
            float pa0, pa1, pa2, pa3, pb0, pb1, pb2, pb3;
            if (fullT) {
                pa0 = ex2f(sacc[2*s][0]);   pa1 = ex2f(sacc[2*s][1]);
                pa2 = ex2f(sacc[2*s][2]);   pa3 = ex2f(sacc[2*s][3]);
                pb0 = ex2f(sacc[2*s+1][0]); pb1 = ex2f(sacc[2*s+1][1]);
                pb2 = ex2f(sacc[2*s+1][2]); pb3 = ex2f(sacc[2*s+1][3]);
            } else {
                const int c0a = n0 + (2 * s) * 8 + (lane & 3) * 2;
                const int c0b = c0a + 8;
                pa0 = (c0a     >= rs0 && c0a     < re0) ? ex2f(sacc[2*s][0])   : 0.f;
                pa1 = (c0a + 1 >= rs0 && c0a + 1 < re0) ? ex2f(sacc[2*s][1])   : 0.f;
                pa2 = (c0a     >= rs1 && c0a     < re1) ? ex2f(sacc[2*s][2])   : 0.f;
                pa3 = (c0a + 1 >= rs1 && c0a + 1 < re1) ? ex2f(sacc[2*s][3])   : 0.f;
                pb0 = (c0b     >= rs0 && c0b     < re0) ? ex2f(sacc[2*s+1][0]) : 0.f;
                pb1 = (c0b + 1 >= rs0 && c0b + 1 < re0) ? ex2f(sacc[2*s+1][1]) : 0.f;
                pb2 = (c0b     >= rs1 && c0b     < re1) ? ex2f(sacc[2*s+1][2]) : 0.f;
                pb3 = (c0b + 1 >= rs1 && c0b + 1 < re1) ? ex2f(sacc[2*s+1][3]) : 0.f;
            }
            l0 += (pa0 + pa1) + (pb0 + pb1);
            l1 += (pa2 + pa3) + (pb2 + pb3);

            uint32_t pah[4];
            pah[0] = pack_h2(pa0, pa1);
            pah[1] = pack_h2(pa2, pa3);
            pah[2] = pack_h2(pb0, pb1);
            pah[3] = pack_h2(pb2, pb3);

#pragma unroll
            for (int pp = 0; pp < 2; ++pp) {
                uint32_t vh0[4], vh1[4];
                const uint32_t off0 = (uint32_t)(s * 16 * KROW + (2 * pp + 0) * 16) * 2;
                const uint32_t off1 = (uint32_t)(s * 16 * KROW + (2 * pp + 1) * 16) * 2;
                LDSM4T(vh0, vfB + off0);
                LDSM4T(vh1, vfB + off1);
                MMAH(oacc[4 * pp + 0], pah, vh0 + 0);
                MMAH(oacc[4 * pp + 1], pah, vh0 + 2);
                MMAH(oacc[4 * pp + 2], pah, vh1 + 0);
                MMAH(oacc[4 * pp + 3], pah, vh1 + 2);
            }
        }
    }

    // ---- epilogue: reduce l across the quad, normalize, store ----
    l0 += __shfl_xor_sync(0xffffffffu, l0, 1);
    l0 += __shfl_xor_sync(0xffffffffu, l0, 2);
    l1 += __shfl_xor_sync(0xffffffffu, l1, 1);
    l1 += __shfl_xor_sync(0xffffffffu, l1, 2);
    const float inv0 = 1.0f / l0;
    const float inv1 = 1.0f / l1;

    float* orow0 = op + (size_t)rloc * DH;
#pragma unroll
    for (int t = 0; t < 8; ++t) {
        const int col = t * 8 + (lane & 3) * 2;
        *(float2*)(orow0 + col)          = make_float2(oacc[t][0] * inv0, oacc[t][1] * inv0);
        *(float2*)(orow0 + 8 * DH + col) = make_float2(oacc[t][2] * inv1, oacc[t][3] * inv1);
    }
}

extern "C" void kernel_launch(void* const* d_in, const int* in_sizes, int n_in,
                              void* d_out, int out_size)
{
    const float* q   = (const float*)d_in[0];
    const float* k   = (const float*)d_in[1];
    const float* v   = (const float*)d_in[2];
    const float* smp = (const float*)d_in[3];
    const int* rsv   = (const int*)d_in[4];
    const int* rev   = (const int*)d_in[5];
    float* out = (float*)d_out;

    const int bh = in_sizes[0] / (NCTX * DH);   // B*H = 32
    cudaFuncSetAttribute(bsattn_mma_kernel,
                         cudaFuncAttributeMaxDynamicSharedMemorySize, SMEM_TOT);
    dim3 grid(NCTX / QM, bh);
    bsattn_mma_kernel<<<grid, NTH, SMEM_TOT>>>(q, k, v, smp, rsv, rev, out);
}